// round 1
// baseline (speedup 1.0000x reference)
#include <cuda_runtime.h>
#include <math.h>

#define N 8192
#define D 512
#define TAU 0.2f

#define BM 128
#define BN 128
#define BK 8
#define TM 8
#define TN 8
// 256 threads = 16x16 microtile grid

// Scratch (device globals: allocation-free per harness rules)
__device__ float g_h1[N * D];        // normalized z1
__device__ float g_h2[N * D];        // normalized z2
__device__ float g_S[4 * N];         // [S11, S12, S21, S22] row sums
__device__ float g_diag[N];          // raw dot h1_i . h2_i

// ---------------------------------------------------------------------------
// Fast exp2 via round-trick + degree-5 Taylor of e^{f ln2}, f in [-0.5, 0.5].
// Avoids MUFU entirely (FFMA/ALU pipes only). |y| <= ~7.3 in this workload.
// Rel err ~3e-6, far below the 1e-3 test threshold.
// ---------------------------------------------------------------------------
__device__ __forceinline__ float exp2_fast(float y) {
    float z = y + 12582912.0f;                 // 1.5*2^23: round-to-nearest int
    int   iz = __float_as_int(z);
    float n = z - 12582912.0f;
    float f = y - n;                           // [-0.5, 0.5]
    float p = 1.3333558e-3f;
    p = fmaf(p, f, 9.6181291e-3f);
    p = fmaf(p, f, 5.5504109e-2f);
    p = fmaf(p, f, 2.4022651e-1f);
    p = fmaf(p, f, 6.9314718e-1f);
    p = fmaf(p, f, 1.0f);
    int e = iz - 0x4B400000;                   // integer part (handles negatives)
    return __int_as_float(__float_as_int(p) + (e << 23));
}

// ---------------------------------------------------------------------------
// Normalize both inputs; also zero the sum buffers and the output scalar.
// grid = 2N blocks of 128 threads; each block handles one row (512 floats).
// ---------------------------------------------------------------------------
__global__ void normalize_kernel(const float* __restrict__ z1,
                                 const float* __restrict__ z2,
                                 float* __restrict__ out) {
    int row = blockIdx.x;
    const float* src;
    float* dst;
    if (row < N) { src = z1 + (size_t)row * D;        dst = g_h1 + (size_t)row * D; }
    else         { src = z2 + (size_t)(row - N) * D;  dst = g_h2 + (size_t)(row - N) * D; }

    int t = threadIdx.x;                        // 128 threads, 4 floats each
    float4 v = ((const float4*)src)[t];
    float s = v.x * v.x + v.y * v.y + v.z * v.z + v.w * v.w;
    #pragma unroll
    for (int o = 16; o; o >>= 1) s += __shfl_xor_sync(0xFFFFFFFFu, s, o);

    __shared__ float ws[4];
    if ((t & 31) == 0) ws[t >> 5] = s;
    __syncthreads();
    float tot = ws[0] + ws[1] + ws[2] + ws[3];
    float inv = rsqrtf(tot);                    // ||z|| ~ 22.6 >> eps always

    float4 o4 = make_float4(v.x * inv, v.y * inv, v.z * inv, v.w * inv);
    ((float4*)dst)[t] = o4;

    // piggyback: zero accumulators + output
    int gidx = blockIdx.x * blockDim.x + t;
    if (gidx < 4 * N) g_S[gidx] = 0.0f;
    if (gidx == 0) out[0] = 0.0f;
}

// ---------------------------------------------------------------------------
// Fused Gram + exp + row/col reduction.
// mode 0: G12 = h1 h2^T (full grid). rowsum->S12, colsum->S21, diag->g_diag.
// mode 1: G11 = h1 h1^T (upper-tri tiles). rowsum->S11, colsum->S11 (off-diag).
// mode 2: G22 = h2 h2^T (upper-tri tiles). rowsum->S22, colsum->S22 (off-diag).
// ---------------------------------------------------------------------------
__global__ __launch_bounds__(256) void gram_kernel(int mode) {
    const int bi = blockIdx.y;                  // row tile
    const int bj = blockIdx.x;                  // col tile
    const bool sym = (mode != 0);
    if (sym && bj < bi) return;                 // upper triangle only

    const float* __restrict__ Ap = (mode == 2) ? g_h2 : g_h1;
    const float* __restrict__ Bp = (mode == 1) ? g_h1 : g_h2;
    float* Srow;
    float* Scol;
    if      (mode == 0) { Srow = g_S + N;     Scol = g_S + 2 * N; }
    else if (mode == 1) { Srow = g_S;         Scol = g_S;         }
    else                { Srow = g_S + 3 * N; Scol = g_S + 3 * N; }

    const bool addCols = (!sym) || (bi != bj);  // skip col-sums on sym diag tile
    const int i0 = bi * BM;
    const int j0 = bj * BN;

    __shared__ float smem[2 * BK * BM];         // As | Bs, reused in epilogue
    float* As = smem;                           // [BK][BM] k-major
    float* Bs = smem + BK * BM;

    const int tid = threadIdx.x;
    const int ty = tid >> 4;                    // 0..15
    const int tx = tid & 15;                    // 0..15
    const int rowBase = ty * TM;
    const int colBase = tx * TN;

    // load mapping: each thread fetches one float4 from A and one from B
    const int lr = tid >> 1;                    // 0..127 row within tile
    const int lk = (tid & 1) * 4;               // 0 or 4

    float acc[TM][TN];
    #pragma unroll
    for (int r = 0; r < TM; ++r)
        #pragma unroll
        for (int c = 0; c < TN; ++c) acc[r][c] = 0.0f;

    for (int kt = 0; kt < D; kt += BK) {
        float4 av = *(const float4*)&Ap[(size_t)(i0 + lr) * D + kt + lk];
        float4 bv = *(const float4*)&Bp[(size_t)(j0 + lr) * D + kt + lk];
        As[(lk + 0) * BM + lr] = av.x;
        As[(lk + 1) * BM + lr] = av.y;
        As[(lk + 2) * BM + lr] = av.z;
        As[(lk + 3) * BM + lr] = av.w;
        Bs[(lk + 0) * BN + lr] = bv.x;
        Bs[(lk + 1) * BN + lr] = bv.y;
        Bs[(lk + 2) * BN + lr] = bv.z;
        Bs[(lk + 3) * BN + lr] = bv.w;
        __syncthreads();

        #pragma unroll
        for (int k = 0; k < BK; ++k) {
            float a[TM], b[TN];
            float4 a0 = *(const float4*)&As[k * BM + rowBase];
            float4 a1 = *(const float4*)&As[k * BM + rowBase + 4];
            float4 b0 = *(const float4*)&Bs[k * BN + colBase];
            float4 b1 = *(const float4*)&Bs[k * BN + colBase + 4];
            a[0]=a0.x; a[1]=a0.y; a[2]=a0.z; a[3]=a0.w;
            a[4]=a1.x; a[5]=a1.y; a[6]=a1.z; a[7]=a1.w;
            b[0]=b0.x; b[1]=b0.y; b[2]=b0.z; b[3]=b0.w;
            b[4]=b1.x; b[5]=b1.y; b[6]=b1.z; b[7]=b1.w;
            #pragma unroll
            for (int r = 0; r < TM; ++r)
                #pragma unroll
                for (int c = 0; c < TN; ++c)
                    acc[r][c] = fmaf(a[r], b[c], acc[r][c]);
        }
        __syncthreads();
    }

    // ---- epilogue: exp(acc/tau), row + col partial sums ----
    const float k_scale = 7.2134752044f;        // log2(e)/TAU
    float rowsum[TM];
    float colsum[TN];
    #pragma unroll
    for (int r = 0; r < TM; ++r) rowsum[r] = 0.0f;
    #pragma unroll
    for (int c = 0; c < TN; ++c) colsum[c] = 0.0f;

    #pragma unroll
    for (int r = 0; r < TM; ++r) {
        #pragma unroll
        for (int c = 0; c < TN; ++c) {
            float dot = acc[r][c];
            float e = exp2_fast(dot * k_scale);
            rowsum[r] += e;
            colsum[c] += e;
            if (mode == 0) {
                int gi = i0 + rowBase + r;
                int gj = j0 + colBase + c;
                if (gi == gj) g_diag[gi] = dot;   // raw dot; scaled in finalize
            }
        }
    }

    // row reduce across tx (16 consecutive lanes -> shfl butterfly)
    #pragma unroll
    for (int r = 0; r < TM; ++r) {
        #pragma unroll
        for (int o = 1; o < 16; o <<= 1)
            rowsum[r] += __shfl_xor_sync(0xFFFFFFFFu, rowsum[r], o);
    }
    if (tx == 0) {
        #pragma unroll
        for (int r = 0; r < TM; ++r)
            atomicAdd(&Srow[i0 + rowBase + r], rowsum[r]);
    }

    // col reduce across ty via shared (reuse tile smem)
    __syncthreads();
    float* red = smem;                          // [16][128] ty-major
    #pragma unroll
    for (int c = 0; c < TN; ++c)
        red[ty * BN + colBase + c] = colsum[c];
    __syncthreads();
    if (addCols && tid < BN) {
        float s = 0.0f;
        #pragma unroll
        for (int q = 0; q < 16; ++q) s += red[q * BN + tid];
        atomicAdd(&Scol[j0 + tid], s);
    }
}

// ---------------------------------------------------------------------------
// Final per-row loss + scalar reduction.
// l1_i = log(S11_i + S12_i - e^5) - d_i/tau
// l2_i = log(S22_i + S21_i - e^5) - d_i/tau
// out  = sum 0.5*(l1+l2)
// ---------------------------------------------------------------------------
__global__ void finalize_kernel(float* __restrict__ out) {
    int i = blockIdx.x * blockDim.x + threadIdx.x;
    float v = 0.0f;
    if (i < N) {
        const float E5 = 148.41315910257660f;   // exp(1/TAU), self-similarity
        float d = g_diag[i] * (1.0f / TAU);
        float den1 = g_S[i]         + g_S[N + i]     - E5;
        float den2 = g_S[3 * N + i] + g_S[2 * N + i] - E5;
        v = 0.5f * ((logf(den1) - d) + (logf(den2) - d));
    }
    #pragma unroll
    for (int o = 16; o; o >>= 1) v += __shfl_xor_sync(0xFFFFFFFFu, v, o);
    __shared__ float ws[8];
    if ((threadIdx.x & 31) == 0) ws[threadIdx.x >> 5] = v;
    __syncthreads();
    if (threadIdx.x == 0) {
        float s = 0.0f;
        #pragma unroll
        for (int q = 0; q < 8; ++q) s += ws[q];
        atomicAdd(out, s);
    }
}

extern "C" void kernel_launch(void* const* d_in, const int* in_sizes, int n_in,
                              void* d_out, int out_size) {
    const float* z1 = (const float*)d_in[0];
    const float* z2 = (const float*)d_in[1];
    float* out = (float*)d_out;

    normalize_kernel<<<2 * N, 128>>>(z1, z2, out);

    dim3 gg(N / BN, N / BM);                    // 64 x 64 tiles
    gram_kernel<<<gg, 256>>>(1);                // G11 (upper tri)
    gram_kernel<<<gg, 256>>>(2);                // G22 (upper tri)
    gram_kernel<<<gg, 256>>>(0);                // G12 (full)

    finalize_kernel<<<N / 256, 256>>>(out);
}

// round 2
// speedup vs baseline: 1.0003x; 1.0003x over previous
#include <cuda_runtime.h>
#include <math.h>

#define N 8192
#define D 512
#define TAU 0.2f

#define BM 128
#define BN 128
#define BK 8
#define TM 8
#define TN 8
// 256 threads = 16x16 microtile grid

// Scratch (device globals: allocation-free per harness rules)
__device__ float g_h1[N * D];        // normalized z1
__device__ float g_h2[N * D];        // normalized z2
__device__ float g_S[4 * N];         // [S11, S12, S21, S22] row sums
__device__ float g_diag[N];          // raw dot h1_i . h2_i

// ---------------------------------------------------------------------------
// Fast exp2 via round-trick + degree-5 Taylor of e^{f ln2}, f in [-0.5, 0.5].
// Avoids MUFU entirely (FFMA/ALU pipes only). |y| <= ~7.3 in this workload.
// Rel err ~3e-6, far below the 1e-3 test threshold.
// ---------------------------------------------------------------------------
__device__ __forceinline__ float exp2_fast(float y) {
    float z = y + 12582912.0f;                 // 1.5*2^23: round-to-nearest int
    int   iz = __float_as_int(z);
    float n = z - 12582912.0f;
    float f = y - n;                           // [-0.5, 0.5]
    float p = 1.3333558e-3f;
    p = fmaf(p, f, 9.6181291e-3f);
    p = fmaf(p, f, 5.5504109e-2f);
    p = fmaf(p, f, 2.4022651e-1f);
    p = fmaf(p, f, 6.9314718e-1f);
    p = fmaf(p, f, 1.0f);
    int e = iz - 0x4B400000;                   // integer part (handles negatives)
    return __int_as_float(__float_as_int(p) + (e << 23));
}

// ---------------------------------------------------------------------------
// Normalize both inputs; also zero the sum buffers and the output scalar.
// grid = 2N blocks of 128 threads; each block handles one row (512 floats).
// ---------------------------------------------------------------------------
__global__ void normalize_kernel(const float* __restrict__ z1,
                                 const float* __restrict__ z2,
                                 float* __restrict__ out) {
    int row = blockIdx.x;
    const float* src;
    float* dst;
    if (row < N) { src = z1 + (size_t)row * D;        dst = g_h1 + (size_t)row * D; }
    else         { src = z2 + (size_t)(row - N) * D;  dst = g_h2 + (size_t)(row - N) * D; }

    int t = threadIdx.x;                        // 128 threads, 4 floats each
    float4 v = ((const float4*)src)[t];
    float s = v.x * v.x + v.y * v.y + v.z * v.z + v.w * v.w;
    #pragma unroll
    for (int o = 16; o; o >>= 1) s += __shfl_xor_sync(0xFFFFFFFFu, s, o);

    __shared__ float ws[4];
    if ((t & 31) == 0) ws[t >> 5] = s;
    __syncthreads();
    float tot = ws[0] + ws[1] + ws[2] + ws[3];
    float inv = rsqrtf(tot);                    // ||z|| ~ 22.6 >> eps always

    float4 o4 = make_float4(v.x * inv, v.y * inv, v.z * inv, v.w * inv);
    ((float4*)dst)[t] = o4;

    // piggyback: zero accumulators + output
    int gidx = blockIdx.x * blockDim.x + t;
    if (gidx < 4 * N) g_S[gidx] = 0.0f;
    if (gidx == 0) out[0] = 0.0f;
}

// ---------------------------------------------------------------------------
// Fused Gram + exp + row/col reduction.
// mode 0: G12 = h1 h2^T (full grid). rowsum->S12, colsum->S21, diag->g_diag.
// mode 1: G11 = h1 h1^T (upper-tri tiles). rowsum->S11, colsum->S11 (off-diag).
// mode 2: G22 = h2 h2^T (upper-tri tiles). rowsum->S22, colsum->S22 (off-diag).
// ---------------------------------------------------------------------------
__global__ __launch_bounds__(256) void gram_kernel(int mode) {
    const int bi = blockIdx.y;                  // row tile
    const int bj = blockIdx.x;                  // col tile
    const bool sym = (mode != 0);
    if (sym && bj < bi) return;                 // upper triangle only

    const float* __restrict__ Ap = (mode == 2) ? g_h2 : g_h1;
    const float* __restrict__ Bp = (mode == 1) ? g_h1 : g_h2;
    float* Srow;
    float* Scol;
    if      (mode == 0) { Srow = g_S + N;     Scol = g_S + 2 * N; }
    else if (mode == 1) { Srow = g_S;         Scol = g_S;         }
    else                { Srow = g_S + 3 * N; Scol = g_S + 3 * N; }

    const bool addCols = (!sym) || (bi != bj);  // skip col-sums on sym diag tile
    const int i0 = bi * BM;
    const int j0 = bj * BN;

    __shared__ float smem[2 * BK * BM];         // As | Bs, reused in epilogue
    float* As = smem;                           // [BK][BM] k-major
    float* Bs = smem + BK * BM;

    const int tid = threadIdx.x;
    const int ty = tid >> 4;                    // 0..15
    const int tx = tid & 15;                    // 0..15
    const int rowBase = ty * TM;
    const int colBase = tx * TN;

    // load mapping: each thread fetches one float4 from A and one from B
    const int lr = tid >> 1;                    // 0..127 row within tile
    const int lk = (tid & 1) * 4;               // 0 or 4

    float acc[TM][TN];
    #pragma unroll
    for (int r = 0; r < TM; ++r)
        #pragma unroll
        for (int c = 0; c < TN; ++c) acc[r][c] = 0.0f;

    for (int kt = 0; kt < D; kt += BK) {
        float4 av = *(const float4*)&Ap[(size_t)(i0 + lr) * D + kt + lk];
        float4 bv = *(const float4*)&Bp[(size_t)(j0 + lr) * D + kt + lk];
        As[(lk + 0) * BM + lr] = av.x;
        As[(lk + 1) * BM + lr] = av.y;
        As[(lk + 2) * BM + lr] = av.z;
        As[(lk + 3) * BM + lr] = av.w;
        Bs[(lk + 0) * BN + lr] = bv.x;
        Bs[(lk + 1) * BN + lr] = bv.y;
        Bs[(lk + 2) * BN + lr] = bv.z;
        Bs[(lk + 3) * BN + lr] = bv.w;
        __syncthreads();

        #pragma unroll
        for (int k = 0; k < BK; ++k) {
            float a[TM], b[TN];
            float4 a0 = *(const float4*)&As[k * BM + rowBase];
            float4 a1 = *(const float4*)&As[k * BM + rowBase + 4];
            float4 b0 = *(const float4*)&Bs[k * BN + colBase];
            float4 b1 = *(const float4*)&Bs[k * BN + colBase + 4];
            a[0]=a0.x; a[1]=a0.y; a[2]=a0.z; a[3]=a0.w;
            a[4]=a1.x; a[5]=a1.y; a[6]=a1.z; a[7]=a1.w;
            b[0]=b0.x; b[1]=b0.y; b[2]=b0.z; b[3]=b0.w;
            b[4]=b1.x; b[5]=b1.y; b[6]=b1.z; b[7]=b1.w;
            #pragma unroll
            for (int r = 0; r < TM; ++r)
                #pragma unroll
                for (int c = 0; c < TN; ++c)
                    acc[r][c] = fmaf(a[r], b[c], acc[r][c]);
        }
        __syncthreads();
    }

    // ---- epilogue: exp(acc/tau), row + col partial sums ----
    const float k_scale = 7.2134752044f;        // log2(e)/TAU
    float rowsum[TM];
    float colsum[TN];
    #pragma unroll
    for (int r = 0; r < TM; ++r) rowsum[r] = 0.0f;
    #pragma unroll
    for (int c = 0; c < TN; ++c) colsum[c] = 0.0f;

    #pragma unroll
    for (int r = 0; r < TM; ++r) {
        #pragma unroll
        for (int c = 0; c < TN; ++c) {
            float dot = acc[r][c];
            float e = exp2_fast(dot * k_scale);
            rowsum[r] += e;
            colsum[c] += e;
            if (mode == 0) {
                int gi = i0 + rowBase + r;
                int gj = j0 + colBase + c;
                if (gi == gj) g_diag[gi] = dot;   // raw dot; scaled in finalize
            }
        }
    }

    // row reduce across tx (16 consecutive lanes -> shfl butterfly)
    #pragma unroll
    for (int r = 0; r < TM; ++r) {
        #pragma unroll
        for (int o = 1; o < 16; o <<= 1)
            rowsum[r] += __shfl_xor_sync(0xFFFFFFFFu, rowsum[r], o);
    }
    if (tx == 0) {
        #pragma unroll
        for (int r = 0; r < TM; ++r)
            atomicAdd(&Srow[i0 + rowBase + r], rowsum[r]);
    }

    // col reduce across ty via shared (reuse tile smem)
    __syncthreads();
    float* red = smem;                          // [16][128] ty-major
    #pragma unroll
    for (int c = 0; c < TN; ++c)
        red[ty * BN + colBase + c] = colsum[c];
    __syncthreads();
    if (addCols && tid < BN) {
        float s = 0.0f;
        #pragma unroll
        for (int q = 0; q < 16; ++q) s += red[q * BN + tid];
        atomicAdd(&Scol[j0 + tid], s);
    }
}

// ---------------------------------------------------------------------------
// Final per-row loss + scalar reduction.
// l1_i = log(S11_i + S12_i - e^5) - d_i/tau
// l2_i = log(S22_i + S21_i - e^5) - d_i/tau
// out  = sum 0.5*(l1+l2)
// ---------------------------------------------------------------------------
__global__ void finalize_kernel(float* __restrict__ out) {
    int i = blockIdx.x * blockDim.x + threadIdx.x;
    float v = 0.0f;
    if (i < N) {
        const float E5 = 148.41315910257660f;   // exp(1/TAU), self-similarity
        float d = g_diag[i] * (1.0f / TAU);
        float den1 = g_S[i]         + g_S[N + i]     - E5;
        float den2 = g_S[3 * N + i] + g_S[2 * N + i] - E5;
        v = 0.5f * ((logf(den1) - d) + (logf(den2) - d));
    }
    #pragma unroll
    for (int o = 16; o; o >>= 1) v += __shfl_xor_sync(0xFFFFFFFFu, v, o);
    __shared__ float ws[8];
    if ((threadIdx.x & 31) == 0) ws[threadIdx.x >> 5] = v;
    __syncthreads();
    if (threadIdx.x == 0) {
        float s = 0.0f;
        #pragma unroll
        for (int q = 0; q < 8; ++q) s += ws[q];
        atomicAdd(out, s);
    }
}

extern "C" void kernel_launch(void* const* d_in, const int* in_sizes, int n_in,
                              void* d_out, int out_size) {
    const float* z1 = (const float*)d_in[0];
    const float* z2 = (const float*)d_in[1];
    float* out = (float*)d_out;

    normalize_kernel<<<2 * N, 128>>>(z1, z2, out);

    dim3 gg(N / BN, N / BM);                    // 64 x 64 tiles
    gram_kernel<<<gg, 256>>>(1);                // G11 (upper tri)
    gram_kernel<<<gg, 256>>>(2);                // G22 (upper tri)
    gram_kernel<<<gg, 256>>>(0);                // G12 (full)

    finalize_kernel<<<N / 256, 256>>>(out);
}

// round 4
// speedup vs baseline: 5.8005x; 5.7987x over previous
#include <cuda_runtime.h>
#include <cuda_bf16.h>
#include <stdint.h>
#include <math.h>

#define N 8192
#define D 512
#define TAU 0.2f

#define BM 128
#define BN 128
#define BK 32                 // bf16 elems per K stage (64 B/row)
#define NK (D / BK)           // 16 stages
#define THREADS 256           // 8 warps: 2 (M) x 4 (N)
#define WM 64
#define WN 32
#define ROWB 80               // padded row stride in bytes (64 data + 16 pad)

__device__ __nv_bfloat16 g_h1b[N * D];
__device__ __nv_bfloat16 g_h2b[N * D];
__device__ float g_S[4 * N];          // S11 | S12 | S21 | S22
__device__ float g_diag[N];

// ---------------- helpers ----------------
__device__ __forceinline__ uint32_t smem_u32(const void* p) {
    uint32_t a;
    asm("{ .reg .u64 t; cvta.to.shared.u64 t, %1; cvt.u32.u64 %0, t; }" : "=r"(a) : "l"(p));
    return a;
}

#define CP_ASYNC16(dst, src) \
    asm volatile("cp.async.cg.shared.global [%0], [%1], 16;" :: "r"(dst), "l"(src))

__device__ __forceinline__ void ldm_x4(uint32_t* r, uint32_t addr) {
    asm volatile("ldmatrix.sync.aligned.m8n8.x4.shared.b16 {%0,%1,%2,%3}, [%4];"
                 : "=r"(r[0]), "=r"(r[1]), "=r"(r[2]), "=r"(r[3]) : "r"(addr));
}
__device__ __forceinline__ void ldm_x2(uint32_t* r, uint32_t addr) {
    asm volatile("ldmatrix.sync.aligned.m8n8.x2.shared.b16 {%0,%1}, [%2];"
                 : "=r"(r[0]), "=r"(r[1]) : "r"(addr));
}
__device__ __forceinline__ void mma_bf16(float* c, const uint32_t* a, const uint32_t* b) {
    asm volatile(
        "mma.sync.aligned.m16n8k16.row.col.f32.bf16.bf16.f32 "
        "{%0,%1,%2,%3}, {%4,%5,%6,%7}, {%8,%9}, {%0,%1,%2,%3};"
        : "+f"(c[0]), "+f"(c[1]), "+f"(c[2]), "+f"(c[3])
        : "r"(a[0]), "r"(a[1]), "r"(a[2]), "r"(a[3]), "r"(b[0]), "r"(b[1]));
}

// fast exp2: FFMA-only, |y| <= ~7.3 here, rel err ~3e-6
__device__ __forceinline__ float exp2_fast(float y) {
    float z = y + 12582912.0f;
    int iz = __float_as_int(z);
    float n = z - 12582912.0f;
    float f = y - n;
    float p = 1.3333558e-3f;
    p = fmaf(p, f, 9.6181291e-3f);
    p = fmaf(p, f, 5.5504109e-2f);
    p = fmaf(p, f, 2.4022651e-1f);
    p = fmaf(p, f, 6.9314718e-1f);
    p = fmaf(p, f, 1.0f);
    int e = iz - 0x4B400000;
    return __int_as_float(__float_as_int(p) + (e << 23));
}

// ---------------- normalize -> bf16 ----------------
__global__ void normalize_kernel(const float* __restrict__ z1,
                                 const float* __restrict__ z2,
                                 float* __restrict__ out) {
    int row = blockIdx.x;
    const float* src;
    __nv_bfloat16* dst;
    if (row < N) { src = z1 + (size_t)row * D;       dst = g_h1b + (size_t)row * D; }
    else         { src = z2 + (size_t)(row - N) * D; dst = g_h2b + (size_t)(row - N) * D; }

    int t = threadIdx.x;
    float4 v = ((const float4*)src)[t];
    float s = v.x * v.x + v.y * v.y + v.z * v.z + v.w * v.w;
    #pragma unroll
    for (int o = 16; o; o >>= 1) s += __shfl_xor_sync(0xFFFFFFFFu, s, o);
    __shared__ float ws[4];
    if ((t & 31) == 0) ws[t >> 5] = s;
    __syncthreads();
    float inv = rsqrtf(ws[0] + ws[1] + ws[2] + ws[3]);

    __nv_bfloat162 p0 = __float22bfloat162_rn(make_float2(v.x * inv, v.y * inv));
    __nv_bfloat162 p1 = __float22bfloat162_rn(make_float2(v.z * inv, v.w * inv));
    uint2 pk;
    pk.x = *(uint32_t*)&p0;
    pk.y = *(uint32_t*)&p1;
    *(uint2*)&dst[4 * t] = pk;

    int gidx = blockIdx.x * blockDim.x + t;
    if (gidx < 4 * N) g_S[gidx] = 0.0f;
    if (gidx == 0) out[0] = 0.0f;
}

// ---------------- fused HMMA Gram + exp + reductions ----------------
// mode 0: G12 full.   rowsum->S12, colsum->S21, diag->g_diag
// mode 1: G11 upper.  rowsum+colsum->S11 (elementwise triangle masks)
// mode 2: G22 upper.  rowsum+colsum->S22
__global__ __launch_bounds__(THREADS) void gram_kernel(int mode) {
    const int bi = blockIdx.y;
    const int bj = blockIdx.x;
    const bool sym = (mode != 0);
    if (sym && bj < bi) return;              // strictly below diagonal

    const __nv_bfloat16* __restrict__ Ap = (mode == 2) ? g_h2b : g_h1b;
    const __nv_bfloat16* __restrict__ Bp = (mode == 1) ? g_h1b : g_h2b;
    float* Srow;
    float* Scol;
    if      (mode == 0) { Srow = g_S + N;     Scol = g_S + 2 * N; }
    else if (mode == 1) { Srow = g_S;         Scol = g_S;         }
    else                { Srow = g_S + 3 * N; Scol = g_S + 3 * N; }

    const int i0 = bi * BM;
    const int j0 = bj * BN;
    const int tid = threadIdx.x;
    const int wid = tid >> 5;
    const int lane = tid & 31;
    const int wm = wid >> 2;                 // 0..1
    const int wn = wid & 3;                  // 0..3

    __shared__ __align__(16) char stage[2][2 * BM * ROWB];   // A|B per stage
    __shared__ float scol[BN];

    const uint32_t sA[2] = { smem_u32(stage[0]), smem_u32(stage[1]) };
    const uint32_t sB[2] = { sA[0] + BM * ROWB, sA[1] + BM * ROWB };

    if (tid < BN) scol[tid] = 0.0f;

    float c[4][4][4];
    #pragma unroll
    for (int mi = 0; mi < 4; ++mi)
        #pragma unroll
        for (int ni = 0; ni < 4; ++ni)
            #pragma unroll
            for (int q = 0; q < 4; ++q) c[mi][ni][q] = 0.0f;

    // ---- stage loader: 2 A-chunks + 2 B-chunks (16B) per thread ----
    auto load_stage = [&](int kt, int buf) {
        #pragma unroll
        for (int q = 0; q < 2; ++q) {
            int ch = tid + q * 256;          // 0..511
            int row = ch >> 2;
            int ci = ch & 3;
            CP_ASYNC16(sA[buf] + row * ROWB + ci * 16,
                       (const char*)(Ap + (size_t)(i0 + row) * D + kt * BK + ci * 8));
            CP_ASYNC16(sB[buf] + row * ROWB + ci * 16,
                       (const char*)(Bp + (size_t)(j0 + row) * D + kt * BK + ci * 8));
        }
        asm volatile("cp.async.commit_group;");
    };

    load_stage(0, 0);

    for (int kt = 0; kt < NK; ++kt) {
        const int buf = kt & 1;
        if (kt + 1 < NK) {
            load_stage(kt + 1, buf ^ 1);
            asm volatile("cp.async.wait_group 1;" ::: "memory");
        } else {
            asm volatile("cp.async.wait_group 0;" ::: "memory");
        }
        __syncthreads();

        #pragma unroll
        for (int ks = 0; ks < 2; ++ks) {     // 2 x k16 per stage
            uint32_t a[4][4], b[4][2];
            #pragma unroll
            for (int mi = 0; mi < 4; ++mi) {
                uint32_t addr = sA[buf] + (wm * WM + mi * 16 + (lane & 15)) * ROWB +
                                ks * 32 + ((lane >> 4) & 1) * 16;
                ldm_x4(a[mi], addr);
            }
            #pragma unroll
            for (int ni = 0; ni < 4; ++ni) {
                uint32_t addr = sB[buf] + (wn * WN + ni * 8 + (lane & 7)) * ROWB +
                                ks * 32 + ((lane >> 3) & 1) * 16;
                ldm_x2(b[ni], addr);
            }
            #pragma unroll
            for (int mi = 0; mi < 4; ++mi)
                #pragma unroll
                for (int ni = 0; ni < 4; ++ni)
                    mma_bf16(c[mi][ni], a[mi], b[ni]);
        }
        __syncthreads();
    }

    // ---- epilogue ----
    const float KS = 7.2134752044f;          // log2(e)/TAU
    const bool diagTile = (mode == 0) && (bi == bj);
    float rsum[4][2];
    float csum[4][2];
    #pragma unroll
    for (int q = 0; q < 4; ++q) { rsum[q][0] = rsum[q][1] = 0.0f; csum[q][0] = csum[q][1] = 0.0f; }

    #pragma unroll
    for (int mi = 0; mi < 4; ++mi) {
        const int gr0 = i0 + wm * WM + mi * 16 + (lane >> 2);
        const int gr1 = gr0 + 8;
        #pragma unroll
        for (int ni = 0; ni < 4; ++ni) {
            const int gc0 = j0 + wn * WN + ni * 8 + (lane & 3) * 2;
            #pragma unroll
            for (int q = 0; q < 4; ++q) {
                const int gr = (q < 2) ? gr0 : gr1;
                const int gc = gc0 + (q & 1);
                float dot = c[mi][ni][q];
                float e = exp2_fast(dot * KS);
                bool rinc = (!sym) || (gc >= gr);
                bool cinc = (!sym) || (gc > gr);
                rsum[mi][q >> 1] += rinc ? e : 0.0f;
                csum[ni][q & 1]  += cinc ? e : 0.0f;
                if (diagTile && gr == gc) g_diag[gr] = dot;
            }
        }
    }

    // row reduce across lanes sharing the same row (lane%4 group: xor 1,2)
    #pragma unroll
    for (int mi = 0; mi < 4; ++mi)
        #pragma unroll
        for (int h = 0; h < 2; ++h) {
            float v = rsum[mi][h];
            v += __shfl_xor_sync(0xFFFFFFFFu, v, 1);
            v += __shfl_xor_sync(0xFFFFFFFFu, v, 2);
            if ((lane & 3) == 0) {
                int gr = i0 + wm * WM + mi * 16 + (lane >> 2) + h * 8;
                atomicAdd(&Srow[gr], v);
            }
        }

    // col reduce across lanes sharing the same cols (lane/4: xor 4,8,16)
    #pragma unroll
    for (int ni = 0; ni < 4; ++ni)
        #pragma unroll
        for (int h = 0; h < 2; ++h) {
            float v = csum[ni][h];
            v += __shfl_xor_sync(0xFFFFFFFFu, v, 4);
            v += __shfl_xor_sync(0xFFFFFFFFu, v, 8);
            v += __shfl_xor_sync(0xFFFFFFFFu, v, 16);
            if (lane < 4) {
                int col = wn * WN + ni * 8 + lane * 2 + h;
                atomicAdd(&scol[col], v);
            }
        }

    __syncthreads();
    if (tid < BN) atomicAdd(&Scol[j0 + tid], scol[tid]);
}

// ---------------- finalize ----------------
__global__ void finalize_kernel(float* __restrict__ out) {
    int i = blockIdx.x * blockDim.x + threadIdx.x;
    float v = 0.0f;
    if (i < N) {
        const float E5 = 148.41315910257660f;   // exp(1/TAU)
        float d = g_diag[i] * (1.0f / TAU);
        float den1 = g_S[i]         + g_S[N + i]     - E5;
        float den2 = g_S[3 * N + i] + g_S[2 * N + i] - E5;
        v = 0.5f * ((logf(den1) - d) + (logf(den2) - d));
    }
    #pragma unroll
    for (int o = 16; o; o >>= 1) v += __shfl_xor_sync(0xFFFFFFFFu, v, o);
    __shared__ float ws[8];
    if ((threadIdx.x & 31) == 0) ws[threadIdx.x >> 5] = v;
    __syncthreads();
    if (threadIdx.x == 0) {
        float s = 0.0f;
        #pragma unroll
        for (int q = 0; q < 8; ++q) s += ws[q];
        atomicAdd(out, s);
    }
}

extern "C" void kernel_launch(void* const* d_in, const int* in_sizes, int n_in,
                              void* d_out, int out_size) {
    const float* z1 = (const float*)d_in[0];
    const float* z2 = (const float*)d_in[1];
    float* out = (float*)d_out;

    normalize_kernel<<<2 * N, 128>>>(z1, z2, out);

    dim3 gg(N / BN, N / BM);                 // 64 x 64
    gram_kernel<<<gg, THREADS>>>(1);
    gram_kernel<<<gg, THREADS>>>(2);
    gram_kernel<<<gg, THREADS>>>(0);

    finalize_kernel<<<N / 256, 256>>>(out);
}

// round 5
// speedup vs baseline: 6.0276x; 1.0392x over previous
#include <cuda_runtime.h>
#include <cuda_bf16.h>
#include <stdint.h>
#include <math.h>

#define N 8192
#define D 512
#define TAU 0.2f

#define BM 128                // block tile rows
#define BN 256                // block tile cols
#define BK 64                 // bf16 K elems per stage (128 B data/row)
#define NKS (D / BK)          // 8 stages
#define THREADS 256           // 8 warps: 2 (M) x 4 (N), warp tile 64x64
#define ROWB 144              // 128 data + 16 pad (conflict-free ldmatrix)

#define A_BYTES (BM * ROWB)           // 18432
#define B_BYTES (BN * ROWB)           // 36864
#define STAGE (A_BYTES + B_BYTES)     // 55296
#define NSTAGE 3
#define SM_COL (NSTAGE * STAGE)       // 165888
#define SMEM_TOTAL (SM_COL + BN * 4)  // +1KB scol

__device__ __nv_bfloat16 g_h1b[N * D];
__device__ __nv_bfloat16 g_h2b[N * D];
__device__ float g_S[4 * N];          // S11 | S12 | S21 | S22
__device__ float g_diag[N];

// ---------------- helpers ----------------
__device__ __forceinline__ uint32_t smem_u32(const void* p) {
    uint32_t a;
    asm("{ .reg .u64 t; cvta.to.shared.u64 t, %1; cvt.u32.u64 %0, t; }" : "=r"(a) : "l"(p));
    return a;
}
#define CP_ASYNC16(dst, src) \
    asm volatile("cp.async.cg.shared.global [%0], [%1], 16;" :: "r"(dst), "l"(src))

__device__ __forceinline__ void ldm_x4(uint32_t* r, uint32_t addr) {
    asm volatile("ldmatrix.sync.aligned.m8n8.x4.shared.b16 {%0,%1,%2,%3}, [%4];"
                 : "=r"(r[0]), "=r"(r[1]), "=r"(r[2]), "=r"(r[3]) : "r"(addr));
}
__device__ __forceinline__ void mma_bf16(float* c, const uint32_t* a,
                                         uint32_t b0, uint32_t b1) {
    asm volatile(
        "mma.sync.aligned.m16n8k16.row.col.f32.bf16.bf16.f32 "
        "{%0,%1,%2,%3}, {%4,%5,%6,%7}, {%8,%9}, {%0,%1,%2,%3};"
        : "+f"(c[0]), "+f"(c[1]), "+f"(c[2]), "+f"(c[3])
        : "r"(a[0]), "r"(a[1]), "r"(a[2]), "r"(a[3]), "r"(b0), "r"(b1));
}

__device__ __forceinline__ float exp2_fast(float y) {
    float z = y + 12582912.0f;
    int iz = __float_as_int(z);
    float n = z - 12582912.0f;
    float f = y - n;
    float p = 1.3333558e-3f;
    p = fmaf(p, f, 9.6181291e-3f);
    p = fmaf(p, f, 5.5504109e-2f);
    p = fmaf(p, f, 2.4022651e-1f);
    p = fmaf(p, f, 6.9314718e-1f);
    p = fmaf(p, f, 1.0f);
    int e = iz - 0x4B400000;
    return __int_as_float(__float_as_int(p) + (e << 23));
}

// ---------------- normalize -> bf16 ----------------
__global__ void normalize_kernel(const float* __restrict__ z1,
                                 const float* __restrict__ z2,
                                 float* __restrict__ out) {
    int row = blockIdx.x;
    const float* src;
    __nv_bfloat16* dst;
    if (row < N) { src = z1 + (size_t)row * D;       dst = g_h1b + (size_t)row * D; }
    else         { src = z2 + (size_t)(row - N) * D; dst = g_h2b + (size_t)(row - N) * D; }

    int t = threadIdx.x;
    float4 v = ((const float4*)src)[t];
    float s = v.x * v.x + v.y * v.y + v.z * v.z + v.w * v.w;
    #pragma unroll
    for (int o = 16; o; o >>= 1) s += __shfl_xor_sync(0xFFFFFFFFu, s, o);
    __shared__ float ws[4];
    if ((t & 31) == 0) ws[t >> 5] = s;
    __syncthreads();
    float inv = rsqrtf(ws[0] + ws[1] + ws[2] + ws[3]);

    __nv_bfloat162 p0 = __float22bfloat162_rn(make_float2(v.x * inv, v.y * inv));
    __nv_bfloat162 p1 = __float22bfloat162_rn(make_float2(v.z * inv, v.w * inv));
    uint2 pk;
    pk.x = *(uint32_t*)&p0;
    pk.y = *(uint32_t*)&p1;
    *(uint2*)&dst[4 * t] = pk;

    int gidx = blockIdx.x * blockDim.x + t;
    if (gidx < 4 * N) g_S[gidx] = 0.0f;
    if (gidx == 0) out[0] = 0.0f;
}

// ---------------- fused HMMA Gram + exp + reductions ----------------
// mode 0: G12 full.   rowsum->S12, colsum->S21, diag->g_diag
// mode 1: G11 upper.  rowsum+colsum->S11 (elementwise triangle masks)
// mode 2: G22 upper.  rowsum+colsum->S22
__global__ __launch_bounds__(THREADS, 1) void gram_kernel(int mode) {
    const int bi = blockIdx.y;                // 0..63 (row tiles of 128)
    const int bj = blockIdx.x;                // 0..31 (col tiles of 256)
    const bool sym = (mode != 0);
    if (sym && (2 * bj + 2) <= bi) return;    // block entirely below diagonal

    const __nv_bfloat16* __restrict__ Ap = (mode == 2) ? g_h2b : g_h1b;
    const __nv_bfloat16* __restrict__ Bp = (mode == 1) ? g_h1b : g_h2b;
    float* Srow;
    float* Scol;
    if      (mode == 0) { Srow = g_S + N;     Scol = g_S + 2 * N; }
    else if (mode == 1) { Srow = g_S;         Scol = g_S;         }
    else                { Srow = g_S + 3 * N; Scol = g_S + 3 * N; }

    const int i0 = bi * BM;
    const int j0 = bj * BN;
    const int tid = threadIdx.x;
    const int wid = tid >> 5;
    const int lane = tid & 31;
    const int wm = wid >> 2;                  // 0..1
    const int wn = wid & 3;                   // 0..3

    extern __shared__ __align__(16) char smem[];
    const uint32_t sb = smem_u32(smem);
    float* scol = (float*)(smem + SM_COL);
    scol[tid] = 0.0f;

    float c[4][8][4];
    #pragma unroll
    for (int mi = 0; mi < 4; ++mi)
        #pragma unroll
        for (int ni = 0; ni < 8; ++ni)
            #pragma unroll
            for (int q = 0; q < 4; ++q) c[mi][ni][q] = 0.0f;

    // stage loader: A 4 chunks + B 8 chunks (16B) per thread
    auto load_stage = [&](int kt, int buf) {
        const uint32_t base = sb + buf * STAGE;
        const int kOff = kt * BK;
        #pragma unroll
        for (int q = 0; q < 4; ++q) {
            int ch = tid + q * 256;           // 0..1023
            int row = ch >> 3;
            int ci = ch & 7;
            CP_ASYNC16(base + row * ROWB + ci * 16,
                       (const char*)(Ap + (size_t)(i0 + row) * D + kOff + ci * 8));
        }
        #pragma unroll
        for (int q = 0; q < 8; ++q) {
            int ch = tid + q * 256;           // 0..2047
            int row = ch >> 3;
            int ci = ch & 7;
            CP_ASYNC16(base + A_BYTES + row * ROWB + ci * 16,
                       (const char*)(Bp + (size_t)(j0 + row) * D + kOff + ci * 8));
        }
        asm volatile("cp.async.commit_group;");
    };

    load_stage(0, 0);
    load_stage(1, 1);

    // hoisted ldmatrix lane addressing
    const uint32_t aLane = (uint32_t)((wm * 64 + (lane & 15)) * ROWB +
                                      ((lane >> 4) & 1) * 16);
    const uint32_t bLane = (uint32_t)((wn * 64 + (lane & 7) + ((lane >> 4) << 3)) * ROWB +
                                      ((lane >> 3) & 1) * 16 + A_BYTES);

    for (int kt = 0; kt < NKS; ++kt) {
        const int buf = kt % NSTAGE;
        if (kt < NKS - 1) asm volatile("cp.async.wait_group 1;" ::: "memory");
        else              asm volatile("cp.async.wait_group 0;" ::: "memory");
        __syncthreads();
        if (kt + 2 < NKS) load_stage(kt + 2, (kt + 2) % NSTAGE);

        const uint32_t stg = sb + buf * STAGE;
        #pragma unroll
        for (int ks = 0; ks < 4; ++ks) {      // 4 x k16 per stage
            uint32_t a[4][4], b[4][4];
            #pragma unroll
            for (int mi = 0; mi < 4; ++mi)
                ldm_x4(a[mi], stg + aLane + mi * 16 * ROWB + ks * 32);
            #pragma unroll
            for (int p = 0; p < 4; ++p)       // each covers 2 n-tiles
                ldm_x4(b[p], stg + bLane + p * 16 * ROWB + ks * 32);
            #pragma unroll
            for (int mi = 0; mi < 4; ++mi)
                #pragma unroll
                for (int p = 0; p < 4; ++p) {
                    mma_bf16(c[mi][2 * p],     a[mi], b[p][0], b[p][1]);
                    mma_bf16(c[mi][2 * p + 1], a[mi], b[p][2], b[p][3]);
                }
        }
    }
    __syncthreads();

    // ---- epilogue ----
    const float KS = 7.2134752044f;           // log2(e)/TAU
    const bool diagTile = (mode == 0) && (bi >= 2 * bj) && (bi < 2 * bj + 2);
    float rsum[4][2];
    float csum[8][2];
    #pragma unroll
    for (int q = 0; q < 4; ++q) rsum[q][0] = rsum[q][1] = 0.0f;
    #pragma unroll
    for (int q = 0; q < 8; ++q) csum[q][0] = csum[q][1] = 0.0f;

    #pragma unroll
    for (int mi = 0; mi < 4; ++mi) {
        const int gr0 = i0 + wm * 64 + mi * 16 + (lane >> 2);
        #pragma unroll
        for (int ni = 0; ni < 8; ++ni) {
            const int gc0 = j0 + wn * 64 + ni * 8 + (lane & 3) * 2;
            #pragma unroll
            for (int q = 0; q < 4; ++q) {
                const int gr = gr0 + ((q >> 1) << 3);
                const int gc = gc0 + (q & 1);
                float dot = c[mi][ni][q];
                float e = exp2_fast(dot * KS);
                rsum[mi][q >> 1] += ((!sym) || (gc >= gr)) ? e : 0.0f;
                csum[ni][q & 1]  += ((!sym) || (gc > gr))  ? e : 0.0f;
                if (diagTile && gr == gc) g_diag[gr] = dot;
            }
        }
    }

    #pragma unroll
    for (int mi = 0; mi < 4; ++mi)
        #pragma unroll
        for (int h = 0; h < 2; ++h) {
            float v = rsum[mi][h];
            v += __shfl_xor_sync(0xFFFFFFFFu, v, 1);
            v += __shfl_xor_sync(0xFFFFFFFFu, v, 2);
            if ((lane & 3) == 0)
                atomicAdd(&Srow[i0 + wm * 64 + mi * 16 + (lane >> 2) + h * 8], v);
        }

    #pragma unroll
    for (int ni = 0; ni < 8; ++ni)
        #pragma unroll
        for (int h = 0; h < 2; ++h) {
            float v = csum[ni][h];
            v += __shfl_xor_sync(0xFFFFFFFFu, v, 4);
            v += __shfl_xor_sync(0xFFFFFFFFu, v, 8);
            v += __shfl_xor_sync(0xFFFFFFFFu, v, 16);
            if (lane < 4)
                atomicAdd(&scol[wn * 64 + ni * 8 + lane * 2 + h], v);
        }

    __syncthreads();
    atomicAdd(&Scol[j0 + tid], scol[tid]);
}

// ---------------- finalize ----------------
__global__ void finalize_kernel(float* __restrict__ out) {
    int i = blockIdx.x * blockDim.x + threadIdx.x;
    float v = 0.0f;
    if (i < N) {
        const float E5 = 148.41315910257660f;  // exp(1/TAU)
        float d = g_diag[i] * (1.0f / TAU);
        float den1 = g_S[i]         + g_S[N + i]     - E5;
        float den2 = g_S[3 * N + i] + g_S[2 * N + i] - E5;
        v = 0.5f * ((logf(den1) - d) + (logf(den2) - d));
    }
    #pragma unroll
    for (int o = 16; o; o >>= 1) v += __shfl_xor_sync(0xFFFFFFFFu, v, o);
    __shared__ float ws[8];
    if ((threadIdx.x & 31) == 0) ws[threadIdx.x >> 5] = v;
    __syncthreads();
    if (threadIdx.x == 0) {
        float s = 0.0f;
        #pragma unroll
        for (int q = 0; q < 8; ++q) s += ws[q];
        atomicAdd(out, s);
    }
}

extern "C" void kernel_launch(void* const* d_in, const int* in_sizes, int n_in,
                              void* d_out, int out_size) {
    const float* z1 = (const float*)d_in[0];
    const float* z2 = (const float*)d_in[1];
    float* out = (float*)d_out;

    static bool cfgd = false;
    if (!cfgd) {
        cudaFuncSetAttribute(gram_kernel,
                             cudaFuncAttributeMaxDynamicSharedMemorySize, SMEM_TOTAL);
        cfgd = true;
    }

    normalize_kernel<<<2 * N, 128>>>(z1, z2, out);

    dim3 gg(N / BN, N / BM);                  // 32 x 64
    gram_kernel<<<gg, THREADS, SMEM_TOTAL>>>(1);
    gram_kernel<<<gg, THREADS, SMEM_TOTAL>>>(2);
    gram_kernel<<<gg, THREADS, SMEM_TOTAL>>>(0);

    finalize_kernel<<<N / 256, 256>>>(out);
}

// round 6
// speedup vs baseline: 7.4052x; 1.2285x over previous
#include <cuda_runtime.h>
#include <cuda_bf16.h>
#include <stdint.h>
#include <math.h>

#define N 8192
#define D 512
#define TAU 0.2f

#define BM 128
#define BN 128
#define BK 64                 // bf16 K elems per stage (128 B/row)
#define NKS (D / BK)          // 8 stages
#define THREADS 256           // 8 warps: 2 (M) x 4 (N), warp tile 64x32
#define ROWB 144              // 128 data + 16 pad

#define A_BYTES (BM * ROWB)            // 18432
#define STAGE (2 * A_BYTES)            // A|B = 36864
#define NSTAGE 3
#define SM_COL (NSTAGE * STAGE)        // 110592
#define SMEM_TOTAL (SM_COL + BN * 4)   // + scol

__device__ __nv_bfloat16 g_h1b[N * D];
__device__ __nv_bfloat16 g_h2b[N * D];
__device__ float g_S[4 * N];          // S11 | S12 | S21 | S22
__device__ float g_diag[N];

// ---------------- helpers ----------------
__device__ __forceinline__ uint32_t smem_u32(const void* p) {
    uint32_t a;
    asm("{ .reg .u64 t; cvta.to.shared.u64 t, %1; cvt.u32.u64 %0, t; }" : "=r"(a) : "l"(p));
    return a;
}
#define CP_ASYNC16(dst, src) \
    asm volatile("cp.async.cg.shared.global [%0], [%1], 16;" :: "r"(dst), "l"(src))

__device__ __forceinline__ void ldm_x4(uint32_t* r, uint32_t addr) {
    asm volatile("ldmatrix.sync.aligned.m8n8.x4.shared.b16 {%0,%1,%2,%3}, [%4];"
                 : "=r"(r[0]), "=r"(r[1]), "=r"(r[2]), "=r"(r[3]) : "r"(addr));
}
__device__ __forceinline__ void mma_bf16(float* c, const uint32_t* a,
                                         uint32_t b0, uint32_t b1) {
    asm volatile(
        "mma.sync.aligned.m16n8k16.row.col.f32.bf16.bf16.f32 "
        "{%0,%1,%2,%3}, {%4,%5,%6,%7}, {%8,%9}, {%0,%1,%2,%3};"
        : "+f"(c[0]), "+f"(c[1]), "+f"(c[2]), "+f"(c[3])
        : "r"(a[0]), "r"(a[1]), "r"(a[2]), "r"(a[3]), "r"(b0), "r"(b1));
}

__device__ __forceinline__ float exp2_fast(float y) {
    float z = y + 12582912.0f;
    int iz = __float_as_int(z);
    float n = z - 12582912.0f;
    float f = y - n;
    float p = 1.3333558e-3f;
    p = fmaf(p, f, 9.6181291e-3f);
    p = fmaf(p, f, 5.5504109e-2f);
    p = fmaf(p, f, 2.4022651e-1f);
    p = fmaf(p, f, 6.9314718e-1f);
    p = fmaf(p, f, 1.0f);
    int e = iz - 0x4B400000;
    return __int_as_float(__float_as_int(p) + (e << 23));
}

// ---------------- normalize -> bf16 (1 warp / row) ----------------
__global__ void normalize_kernel(const float* __restrict__ z1,
                                 const float* __restrict__ z2,
                                 float* __restrict__ out) {
    int row = blockIdx.x * 8 + (threadIdx.x >> 5);
    int lane = threadIdx.x & 31;
    const float* src;
    __nv_bfloat16* dst;
    if (row < N) { src = z1 + (size_t)row * D;       dst = g_h1b + (size_t)row * D; }
    else         { src = z2 + (size_t)(row - N) * D; dst = g_h2b + (size_t)(row - N) * D; }

    float4 v[4];
    float s = 0.0f;
    #pragma unroll
    for (int q = 0; q < 4; ++q) {
        v[q] = ((const float4*)src)[lane + q * 32];
        s += v[q].x * v[q].x + v[q].y * v[q].y + v[q].z * v[q].z + v[q].w * v[q].w;
    }
    #pragma unroll
    for (int o = 16; o; o >>= 1) s += __shfl_xor_sync(0xFFFFFFFFu, s, o);
    float inv = rsqrtf(s);

    #pragma unroll
    for (int q = 0; q < 4; ++q) {
        __nv_bfloat162 p0 = __float22bfloat162_rn(make_float2(v[q].x * inv, v[q].y * inv));
        __nv_bfloat162 p1 = __float22bfloat162_rn(make_float2(v[q].z * inv, v[q].w * inv));
        uint2 pk;
        pk.x = *(uint32_t*)&p0;
        pk.y = *(uint32_t*)&p1;
        *(uint2*)&dst[4 * (lane + q * 32)] = pk;
    }

    int gidx = blockIdx.x * blockDim.x + threadIdx.x;
    if (gidx < 4 * N) g_S[gidx] = 0.0f;
    if (gidx == 0) out[0] = 0.0f;
}

// ---------------- fused HMMA Gram + exp + reductions ----------------
// z=0: G11 upper (mode1). z=1: G22 upper (mode2). z=2: G12 full (mode0).
__global__ __launch_bounds__(THREADS, 2) void gram_kernel() {
    const int mode = (blockIdx.z == 2) ? 0 : (int)blockIdx.z + 1;
    const int bi = blockIdx.y;
    const int bj = blockIdx.x;
    const bool sym = (mode != 0);
    if (sym && bj < bi) return;

    const __nv_bfloat16* __restrict__ Ap = (mode == 2) ? g_h2b : g_h1b;
    const __nv_bfloat16* __restrict__ Bp = (mode == 1) ? g_h1b : g_h2b;
    float* Srow;
    float* Scol;
    if      (mode == 0) { Srow = g_S + N;     Scol = g_S + 2 * N; }
    else if (mode == 1) { Srow = g_S;         Scol = g_S;         }
    else                { Srow = g_S + 3 * N; Scol = g_S + 3 * N; }

    const int i0 = bi * BM;
    const int j0 = bj * BN;
    const int tid = threadIdx.x;
    const int wid = tid >> 5;
    const int lane = tid & 31;
    const int wm = wid >> 2;                  // 0..1
    const int wn = wid & 3;                   // 0..3

    extern __shared__ __align__(16) char smem[];
    const uint32_t sb = smem_u32(smem);
    float* scol = (float*)(smem + SM_COL);
    if (tid < BN) scol[tid] = 0.0f;

    float c[4][4][4];
    #pragma unroll
    for (int mi = 0; mi < 4; ++mi)
        #pragma unroll
        for (int ni = 0; ni < 4; ++ni)
            #pragma unroll
            for (int q = 0; q < 4; ++q) c[mi][ni][q] = 0.0f;

    // stage loader: 4 A-chunks + 4 B-chunks (16B) per thread
    auto load_stage = [&](int kt, int buf) {
        const uint32_t base = sb + buf * STAGE;
        const int kOff = kt * BK;
        #pragma unroll
        for (int q = 0; q < 4; ++q) {
            int ch = tid + q * 256;           // 0..1023
            int row = ch >> 3;
            int ci = ch & 7;
            CP_ASYNC16(base + row * ROWB + ci * 16,
                       (const char*)(Ap + (size_t)(i0 + row) * D + kOff + ci * 8));
            CP_ASYNC16(base + A_BYTES + row * ROWB + ci * 16,
                       (const char*)(Bp + (size_t)(j0 + row) * D + kOff + ci * 8));
        }
        asm volatile("cp.async.commit_group;");
    };

    load_stage(0, 0);
    load_stage(1, 1);

    const uint32_t aLane = (uint32_t)((wm * 64 + (lane & 15)) * ROWB +
                                      ((lane >> 4) & 1) * 16);
    const uint32_t bLane = (uint32_t)((wn * 32 + (lane & 7) + ((lane >> 4) << 3)) * ROWB +
                                      ((lane >> 3) & 1) * 16 + A_BYTES);

    for (int kt = 0; kt < NKS; ++kt) {
        const int buf = kt % NSTAGE;
        if (kt < NKS - 1) asm volatile("cp.async.wait_group 1;" ::: "memory");
        else              asm volatile("cp.async.wait_group 0;" ::: "memory");
        __syncthreads();
        if (kt + 2 < NKS) load_stage(kt + 2, (kt + 2) % NSTAGE);

        const uint32_t stg = sb + buf * STAGE;
        #pragma unroll
        for (int ks = 0; ks < 4; ++ks) {      // 4 x k16 per stage
            uint32_t a[4][4], b[2][4];
            #pragma unroll
            for (int mi = 0; mi < 4; ++mi)
                ldm_x4(a[mi], stg + aLane + mi * 16 * ROWB + ks * 32);
            #pragma unroll
            for (int p = 0; p < 2; ++p)       // each covers 2 n-tiles
                ldm_x4(b[p], stg + bLane + p * 16 * ROWB + ks * 32);
            #pragma unroll
            for (int mi = 0; mi < 4; ++mi)
                #pragma unroll
                for (int p = 0; p < 2; ++p) {
                    mma_bf16(c[mi][2 * p],     a[mi], b[p][0], b[p][1]);
                    mma_bf16(c[mi][2 * p + 1], a[mi], b[p][2], b[p][3]);
                }
        }
    }
    __syncthreads();

    // ---- epilogue ----
    const float KS = 7.2134752044f;           // log2(e)/TAU
    const bool diagTile = (mode == 0) && (bi == bj);
    float rsum[4][2];
    float csum[4][2];
    #pragma unroll
    for (int q = 0; q < 4; ++q) {
        rsum[q][0] = rsum[q][1] = 0.0f;
        csum[q][0] = csum[q][1] = 0.0f;
    }

    #pragma unroll
    for (int mi = 0; mi < 4; ++mi) {
        const int gr0 = i0 + wm * 64 + mi * 16 + (lane >> 2);
        #pragma unroll
        for (int ni = 0; ni < 4; ++ni) {
            const int gc0 = j0 + wn * 32 + ni * 8 + (lane & 3) * 2;
            #pragma unroll
            for (int q = 0; q < 4; ++q) {
                const int gr = gr0 + ((q >> 1) << 3);
                const int gc = gc0 + (q & 1);
                float dot = c[mi][ni][q];
                float e = exp2_fast(dot * KS);
                rsum[mi][q >> 1] += ((!sym) || (gc >= gr)) ? e : 0.0f;
                csum[ni][q & 1]  += ((!sym) || (gc > gr))  ? e : 0.0f;
                if (diagTile && gr == gc) g_diag[gr] = dot;
            }
        }
    }

    #pragma unroll
    for (int mi = 0; mi < 4; ++mi)
        #pragma unroll
        for (int h = 0; h < 2; ++h) {
            float v = rsum[mi][h];
            v += __shfl_xor_sync(0xFFFFFFFFu, v, 1);
            v += __shfl_xor_sync(0xFFFFFFFFu, v, 2);
            if ((lane & 3) == 0)
                atomicAdd(&Srow[i0 + wm * 64 + mi * 16 + (lane >> 2) + h * 8], v);
        }

    #pragma unroll
    for (int ni = 0; ni < 4; ++ni)
        #pragma unroll
        for (int h = 0; h < 2; ++h) {
            float v = csum[ni][h];
            v += __shfl_xor_sync(0xFFFFFFFFu, v, 4);
            v += __shfl_xor_sync(0xFFFFFFFFu, v, 8);
            v += __shfl_xor_sync(0xFFFFFFFFu, v, 16);
            if (lane < 4)
                atomicAdd(&scol[wn * 32 + ni * 8 + lane * 2 + h], v);
        }

    __syncthreads();
    if (tid < BN) atomicAdd(&Scol[j0 + tid], scol[tid]);
}

// ---------------- finalize ----------------
__global__ void finalize_kernel(float* __restrict__ out) {
    int i = blockIdx.x * blockDim.x + threadIdx.x;
    float v = 0.0f;
    if (i < N) {
        const float E5 = 148.41315910257660f;  // exp(1/TAU)
        float d = g_diag[i] * (1.0f / TAU);
        float den1 = g_S[i]         + g_S[N + i]     - E5;
        float den2 = g_S[3 * N + i] + g_S[2 * N + i] - E5;
        v = 0.5f * ((logf(den1) - d) + (logf(den2) - d));
    }
    #pragma unroll
    for (int o = 16; o; o >>= 1) v += __shfl_xor_sync(0xFFFFFFFFu, v, o);
    __shared__ float ws[8];
    if ((threadIdx.x & 31) == 0) ws[threadIdx.x >> 5] = v;
    __syncthreads();
    if (threadIdx.x == 0) {
        float s = 0.0f;
        #pragma unroll
        for (int q = 0; q < 8; ++q) s += ws[q];
        atomicAdd(out, s);
    }
}

extern "C" void kernel_launch(void* const* d_in, const int* in_sizes, int n_in,
                              void* d_out, int out_size) {
    const float* z1 = (const float*)d_in[0];
    const float* z2 = (const float*)d_in[1];
    float* out = (float*)d_out;

    static bool cfgd = false;
    if (!cfgd) {
        cudaFuncSetAttribute(gram_kernel,
                             cudaFuncAttributeMaxDynamicSharedMemorySize, SMEM_TOTAL);
        cfgd = true;
    }

    normalize_kernel<<<2 * N / 8, 256>>>(z1, z2, out);

    dim3 gg(N / BN, N / BM, 3);               // 64 x 64 x {G11,G22,G12}
    gram_kernel<<<gg, THREADS, SMEM_TOTAL>>>();

    finalize_kernel<<<N / 256, 256>>>(out);
}